// round 1
// baseline (speedup 1.0000x reference)
#include <cuda_runtime.h>
#include <cstdint>

#define NROWS 4194304
#define DVAL 8
#define BLOCK 256
#define FLT_MAX_C 3.402823466e+38f

__global__ void zero_out_kernel(float* out) {
    out[0] = 0.0f;
}

__global__ void __launch_bounds__(BLOCK)
multidepth_mse_kernel(const float* __restrict__ outputs,
                      const float* __restrict__ targets,
                      float* __restrict__ out) {
    int row = blockIdx.x * BLOCK + threadIdx.x;

    float acc = 0.0f;
    if (row < NROWS) {
        const float4* op = reinterpret_cast<const float4*>(outputs) + (size_t)row * 2;
        const float4* tp = reinterpret_cast<const float4*>(targets) + (size_t)row * 2;
        float4 o0 = op[0];
        float4 o1 = op[1];
        float4 t0 = tp[0];
        float4 t1 = tp[1];

        float o[8] = {o0.x, o0.y, o0.z, o0.w, o1.x, o1.y, o1.z, o1.w};
        float t[8] = {t0.x, t0.y, t0.z, t0.w, t1.x, t1.y, t1.z, t1.w};

        #pragma unroll
        for (int i = 0; i < DVAL; i++) {
            float tc = t[i];
            // argmin over remaining outputs; first-min-wins (strict <) to match jnp.argmin
            float bestd = fabsf(o[0] - tc);
            float bestv = o[0];
            int   bi    = 0;
            #pragma unroll
            for (int j = 1; j < DVAL; j++) {
                float dd = fabsf(o[j] - tc);
                bool lt = dd < bestd;
                bestd = lt ? dd   : bestd;
                bestv = lt ? o[j] : bestv;
                bi    = lt ? j    : bi;
            }
            // knock out the selected slot (FLT_MAX == jnp.finfo(float32).max)
            #pragma unroll
            for (int j = 0; j < DVAL; j++)
                if (j == bi) o[j] = FLT_MAX_C;

            // targets==IGNORE(0): seltarget = output -> diff 0 (stop_gradient irrelevant fwd)
            float diff = bestv - tc;
            if (tc != 0.0f) acc += diff * diff;
        }
    }

    // warp reduction
    #pragma unroll
    for (int off = 16; off > 0; off >>= 1)
        acc += __shfl_down_sync(0xffffffffu, acc, off);

    __shared__ float warp_sums[BLOCK / 32];
    int lane = threadIdx.x & 31;
    int wid  = threadIdx.x >> 5;
    if (lane == 0) warp_sums[wid] = acc;
    __syncthreads();

    if (wid == 0) {
        acc = (lane < BLOCK / 32) ? warp_sums[lane] : 0.0f;
        #pragma unroll
        for (int off = 16; off > 0; off >>= 1)
            acc += __shfl_down_sync(0xffffffffu, acc, off);
        if (lane == 0) {
            const float inv_total = 1.0f / (float)((long long)NROWS * DVAL);
            atomicAdd(out, acc * inv_total);
        }
    }
}

extern "C" void kernel_launch(void* const* d_in, const int* in_sizes, int n_in,
                              void* d_out, int out_size) {
    const float* outputs = (const float*)d_in[0];
    const float* targets = (const float*)d_in[1];
    float* out = (float*)d_out;

    zero_out_kernel<<<1, 1>>>(out);

    int blocks = (NROWS + BLOCK - 1) / BLOCK;
    multidepth_mse_kernel<<<blocks, BLOCK>>>(outputs, targets, out);
}

// round 3
// speedup vs baseline: 1.4752x; 1.4752x over previous
#include <cuda_runtime.h>
#include <cstdint>

#define NROWS 4194304
#define HALFN (NROWS / 2)
#define DVAL 8
#define BLOCK 256
#define FLT_MAX_C 3.402823466e+38f
#define DEAD_THRESH 1.0e30f

__global__ void zero_out_kernel(float* out) {
    out[0] = 0.0f;
}

__device__ __forceinline__ float row_loss(float4 ov0, float4 ov1, float4 tv0, float4 tv1) {
    float o[8] = {ov0.x, ov0.y, ov0.z, ov0.w, ov1.x, ov1.y, ov1.z, ov1.w};
    float t[8] = {tv0.x, tv0.y, tv0.z, tv0.w, tv1.x, tv1.y, tv1.z, tv1.w};

    float acc = 0.0f;
    #pragma unroll
    for (int i = 0; i < DVAL; i++) {
        float tc = t[i];
        float d0 = o[0] - tc, d1 = o[1] - tc, d2 = o[2] - tc, d3 = o[3] - tc;
        float d4 = o[4] - tc, d5 = o[5] - tc, d6 = o[6] - tc, d7 = o[7] - tc;

        // min |d_j| via FMNMX tree (index-free argmin; |src| modifier is free)
        float m01 = fminf(fabsf(d0), fabsf(d1));
        float m23 = fminf(fabsf(d2), fabsf(d3));
        float m45 = fminf(fabsf(d4), fabsf(d5));
        float m67 = fminf(fabsf(d6), fabsf(d7));
        float bestd = fminf(fminf(m01, m23), fminf(m45, m67));

        // targets==IGNORE(0) -> zero contribution.
        // bestd >= DEAD_THRESH means every column is knocked out (can only
        // happen after an exact-tie double knockout) -> contribute 0, never inf.
        if ((tc != 0.0f) && (bestd < DEAD_THRESH))
            acc = fmaf(bestd, bestd, acc);

        // knockout by value match (FLT_MAX == jnp.finfo(float32).max).
        // Dead cols have |FLT_MAX - tc| == FLT_MAX >> any alive bestd.
        if (i < DVAL - 1) {
            o[0] = (fabsf(d0) == bestd) ? FLT_MAX_C : o[0];
            o[1] = (fabsf(d1) == bestd) ? FLT_MAX_C : o[1];
            o[2] = (fabsf(d2) == bestd) ? FLT_MAX_C : o[2];
            o[3] = (fabsf(d3) == bestd) ? FLT_MAX_C : o[3];
            o[4] = (fabsf(d4) == bestd) ? FLT_MAX_C : o[4];
            o[5] = (fabsf(d5) == bestd) ? FLT_MAX_C : o[5];
            o[6] = (fabsf(d6) == bestd) ? FLT_MAX_C : o[6];
            o[7] = (fabsf(d7) == bestd) ? FLT_MAX_C : o[7];
        }
    }
    return acc;
}

__global__ void __launch_bounds__(BLOCK)
multidepth_mse_kernel(const float* __restrict__ outputs,
                      const float* __restrict__ targets,
                      float* __restrict__ out) {
    int tid = blockIdx.x * BLOCK + threadIdx.x;
    int rowA = tid;          // [0, HALFN)
    int rowB = tid + HALFN;  // [HALFN, NROWS)

    const float4* opA = reinterpret_cast<const float4*>(outputs) + (size_t)rowA * 2;
    const float4* tpA = reinterpret_cast<const float4*>(targets) + (size_t)rowA * 2;
    const float4* opB = reinterpret_cast<const float4*>(outputs) + (size_t)rowB * 2;
    const float4* tpB = reinterpret_cast<const float4*>(targets) + (size_t)rowB * 2;

    // Front-batch 8 x LDG.128 for MLP
    float4 oA0 = opA[0], oA1 = opA[1];
    float4 tA0 = tpA[0], tA1 = tpA[1];
    float4 oB0 = opB[0], oB1 = opB[1];
    float4 tB0 = tpB[0], tB1 = tpB[1];

    float acc = row_loss(oA0, oA1, tA0, tA1) + row_loss(oB0, oB1, tB0, tB1);

    // warp reduction
    #pragma unroll
    for (int off = 16; off > 0; off >>= 1)
        acc += __shfl_down_sync(0xffffffffu, acc, off);

    __shared__ float warp_sums[BLOCK / 32];
    int lane = threadIdx.x & 31;
    int wid  = threadIdx.x >> 5;
    if (lane == 0) warp_sums[wid] = acc;
    __syncthreads();

    if (wid == 0) {
        acc = (lane < BLOCK / 32) ? warp_sums[lane] : 0.0f;
        #pragma unroll
        for (int off = 16; off > 0; off >>= 1)
            acc += __shfl_down_sync(0xffffffffu, acc, off);
        if (lane == 0) {
            const float inv_total = 1.0f / (float)((long long)NROWS * DVAL);
            atomicAdd(out, acc * inv_total);
        }
    }
}

extern "C" void kernel_launch(void* const* d_in, const int* in_sizes, int n_in,
                              void* d_out, int out_size) {
    const float* outputs = (const float*)d_in[0];
    const float* targets = (const float*)d_in[1];
    float* out = (float*)d_out;

    zero_out_kernel<<<1, 1>>>(out);

    int blocks = HALFN / BLOCK;  // 8192
    multidepth_mse_kernel<<<blocks, BLOCK>>>(outputs, targets, out);
}

// round 4
// speedup vs baseline: 1.6860x; 1.1430x over previous
#include <cuda_runtime.h>
#include <cstdint>

#define NROWS 4194304
#define HALFN (NROWS / 2)
#define DVAL 8
#define BLOCK 256
#define BIGKNOCK 1.0e38f
#define DEAD_THRESH 1.0e30f

__global__ void zero_out_kernel(float* out) {
    out[0] = 0.0f;
}

// set.eq returns 1.0f / 0.0f in a float register (FSET-class, single alu op)
__device__ __forceinline__ float fset_eq(float a, float b) {
    float r;
    asm("set.eq.f32.f32 %0, %1, %2;" : "=f"(r) : "f"(a), "f"(b));
    return r;
}

__device__ __forceinline__ float row_loss(float4 ov0, float4 ov1, float4 tv0, float4 tv1) {
    float t[8] = {tv0.x, tv0.y, tv0.z, tv0.w, tv1.x, tv1.y, tv1.z, tv1.w};
    // live diffs vs current target column; advanced by delta each step
    float d[8] = {ov0.x - t[0], ov0.y - t[0], ov0.z - t[0], ov0.w - t[0],
                  ov1.x - t[0], ov1.y - t[0], ov1.z - t[0], ov1.w - t[0]};

    float acc = 0.0f;
    #pragma unroll
    for (int i = 0; i < DVAL; i++) {
        float tc = t[i];

        // min |d_j| via FMNMX tree (|src| modifier is free)
        float m01 = fminf(fabsf(d[0]), fabsf(d[1]));
        float m23 = fminf(fabsf(d[2]), fabsf(d[3]));
        float m45 = fminf(fabsf(d[4]), fabsf(d[5]));
        float m67 = fminf(fabsf(d[6]), fabsf(d[7]));
        float bestd = fminf(fminf(m01, m23), fminf(m45, m67));

        // targets==IGNORE(0) -> zero contribution.
        // All-dead (exact-tie double-knockouts) only possible from step 4 on:
        // each step knocks >=1, ties knock 2; 8 dead needs >=4 steps done.
        float w;
        if (i < 4)
            w = (tc != 0.0f) ? bestd : 0.0f;
        else
            w = ((tc != 0.0f) && (bestd < DEAD_THRESH)) ? bestd : 0.0f;
        acc = fmaf(w, w, acc);

        // knockout (value match) folded into delta-advance, on the fma pipe:
        // eq_j in {0,1}; knocked column jumps to ~1e38 and stays there since
        // subsequent O(1) deltas round away.
        if (i < DVAL - 1) {
            float delta = tc - t[i + 1];
            #pragma unroll
            for (int j = 0; j < DVAL; j++) {
                float eq = fset_eq(fabsf(d[j]), bestd);
                d[j] = fmaf(eq, BIGKNOCK, d[j] + delta);
            }
        }
    }
    return acc;
}

__global__ void __launch_bounds__(BLOCK)
multidepth_mse_kernel(const float* __restrict__ outputs,
                      const float* __restrict__ targets,
                      float* __restrict__ out) {
    int tid = blockIdx.x * BLOCK + threadIdx.x;
    int rowA = tid;          // [0, HALFN)
    int rowB = tid + HALFN;  // [HALFN, NROWS)

    const float4* opA = reinterpret_cast<const float4*>(outputs) + (size_t)rowA * 2;
    const float4* tpA = reinterpret_cast<const float4*>(targets) + (size_t)rowA * 2;
    const float4* opB = reinterpret_cast<const float4*>(outputs) + (size_t)rowB * 2;
    const float4* tpB = reinterpret_cast<const float4*>(targets) + (size_t)rowB * 2;

    // Front-batch 8 x LDG.128 for MLP
    float4 oA0 = opA[0], oA1 = opA[1];
    float4 tA0 = tpA[0], tA1 = tpA[1];
    float4 oB0 = opB[0], oB1 = opB[1];
    float4 tB0 = tpB[0], tB1 = tpB[1];

    float acc = row_loss(oA0, oA1, tA0, tA1) + row_loss(oB0, oB1, tB0, tB1);

    // warp reduction
    #pragma unroll
    for (int off = 16; off > 0; off >>= 1)
        acc += __shfl_down_sync(0xffffffffu, acc, off);

    __shared__ float warp_sums[BLOCK / 32];
    int lane = threadIdx.x & 31;
    int wid  = threadIdx.x >> 5;
    if (lane == 0) warp_sums[wid] = acc;
    __syncthreads();

    if (wid == 0) {
        acc = (lane < BLOCK / 32) ? warp_sums[lane] : 0.0f;
        #pragma unroll
        for (int off = 16; off > 0; off >>= 1)
            acc += __shfl_down_sync(0xffffffffu, acc, off);
        if (lane == 0) {
            const float inv_total = 1.0f / (float)((long long)NROWS * DVAL);
            atomicAdd(out, acc * inv_total);
        }
    }
}

extern "C" void kernel_launch(void* const* d_in, const int* in_sizes, int n_in,
                              void* d_out, int out_size) {
    const float* outputs = (const float*)d_in[0];
    const float* targets = (const float*)d_in[1];
    float* out = (float*)d_out;

    zero_out_kernel<<<1, 1>>>(out);

    int blocks = HALFN / BLOCK;  // 8192
    multidepth_mse_kernel<<<blocks, BLOCK>>>(outputs, targets, out);
}

// round 5
// speedup vs baseline: 1.6927x; 1.0039x over previous
#include <cuda_runtime.h>
#include <cstdint>

#define NROWS 4194304
#define QN (NROWS / 4)
#define DVAL 8
#define BLOCK 256
#define GRID (QN / BLOCK)   // 4096
#define BIGKNOCK 1.0e38f
#define DEAD_THRESH 1.0e30f

__device__ float    g_scratch = 0.0f;
__device__ unsigned g_count   = 0u;

// set.eq returns 1.0f / 0.0f in a float register
__device__ __forceinline__ float fset_eq(float a, float b) {
    float r;
    asm("set.eq.f32.f32 %0, %1, %2;" : "=f"(r) : "f"(a), "f"(b));
    return r;
}

__device__ __forceinline__ float row_loss(float4 ov0, float4 ov1, float4 tv0, float4 tv1) {
    float t[8] = {tv0.x, tv0.y, tv0.z, tv0.w, tv1.x, tv1.y, tv1.z, tv1.w};
    // live diffs vs current target column; advanced by delta each step
    float d[8] = {ov0.x - t[0], ov0.y - t[0], ov0.z - t[0], ov0.w - t[0],
                  ov1.x - t[0], ov1.y - t[0], ov1.z - t[0], ov1.w - t[0]};

    float acc = 0.0f;
    #pragma unroll
    for (int i = 0; i < DVAL; i++) {
        float tc = t[i];

        // min |d_j| via FMNMX tree (|src| modifier is free)
        float m01 = fminf(fabsf(d[0]), fabsf(d[1]));
        float m23 = fminf(fabsf(d[2]), fabsf(d[3]));
        float m45 = fminf(fabsf(d[4]), fabsf(d[5]));
        float m67 = fminf(fabsf(d[6]), fabsf(d[7]));
        float bestd = fminf(fminf(m01, m23), fminf(m45, m67));

        // targets==IGNORE(0) -> zero contribution.
        // All-dead (exact-tie double-knockouts) only possible from step 4 on.
        float w;
        if (i < 4)
            w = (tc != 0.0f) ? bestd : 0.0f;
        else
            w = ((tc != 0.0f) && (bestd < DEAD_THRESH)) ? bestd : 0.0f;
        acc = fmaf(w, w, acc);

        // knockout (value match) folded into delta-advance on the fma pipe
        if (i < DVAL - 1) {
            float delta = tc - t[i + 1];
            #pragma unroll
            for (int j = 0; j < DVAL; j++) {
                float eq = fset_eq(fabsf(d[j]), bestd);
                d[j] = fmaf(eq, BIGKNOCK, d[j] + delta);
            }
        }
    }
    return acc;
}

__global__ void __launch_bounds__(BLOCK)
multidepth_mse_kernel(const float* __restrict__ outputs,
                      const float* __restrict__ targets,
                      float* __restrict__ out) {
    int tid = blockIdx.x * BLOCK + threadIdx.x;

    const float4* ob = reinterpret_cast<const float4*>(outputs);
    const float4* tb = reinterpret_cast<const float4*>(targets);

    size_t rA = (size_t)tid * 2;
    size_t rB = (size_t)(tid + QN) * 2;
    size_t rC = (size_t)(tid + 2 * QN) * 2;
    size_t rD = (size_t)(tid + 3 * QN) * 2;

    // Front-batch 16 x LDG.128 for MLP
    float4 oA0 = ob[rA], oA1 = ob[rA + 1], tA0 = tb[rA], tA1 = tb[rA + 1];
    float4 oB0 = ob[rB], oB1 = ob[rB + 1], tB0 = tb[rB], tB1 = tb[rB + 1];
    float4 oC0 = ob[rC], oC1 = ob[rC + 1], tC0 = tb[rC], tC1 = tb[rC + 1];
    float4 oD0 = ob[rD], oD1 = ob[rD + 1], tD0 = tb[rD], tD1 = tb[rD + 1];

    float acc = row_loss(oA0, oA1, tA0, tA1)
              + row_loss(oB0, oB1, tB0, tB1)
              + row_loss(oC0, oC1, tC0, tC1)
              + row_loss(oD0, oD1, tD0, tD1);

    // warp reduction
    #pragma unroll
    for (int off = 16; off > 0; off >>= 1)
        acc += __shfl_down_sync(0xffffffffu, acc, off);

    __shared__ float warp_sums[BLOCK / 32];
    int lane = threadIdx.x & 31;
    int wid  = threadIdx.x >> 5;
    if (lane == 0) warp_sums[wid] = acc;
    __syncthreads();

    if (wid == 0) {
        acc = (lane < BLOCK / 32) ? warp_sums[lane] : 0.0f;
        #pragma unroll
        for (int off = 16; off > 0; off >>= 1)
            acc += __shfl_down_sync(0xffffffffu, acc, off);
        if (lane == 0) {
            // Single-kernel finish: last block to arrive publishes the result
            // and resets scratch state for the next (graph-replayed) launch.
            float old = atomicAdd(&g_scratch, acc);
            __threadfence();
            unsigned ticket = atomicInc(&g_count, GRID - 1);  // wraps to 0 on last
            if (ticket == GRID - 1) {
                const float inv_total = 1.0f / (float)((long long)NROWS * DVAL);
                out[0] = (old + acc) * inv_total;
                g_scratch = 0.0f;  // visible before next launch (kernel boundary)
            }
        }
    }
}

extern "C" void kernel_launch(void* const* d_in, const int* in_sizes, int n_in,
                              void* d_out, int out_size) {
    const float* outputs = (const float*)d_in[0];
    const float* targets = (const float*)d_in[1];
    float* out = (float*)d_out;

    multidepth_mse_kernel<<<GRID, BLOCK>>>(outputs, targets, out);
}